// round 14
// baseline (speedup 1.0000x reference)
#include <cuda_runtime.h>
#include <cstdint>

#define N_NODES 100000
#define N_EDGES 1600000
#define D 128
#define A_DIM 512
#define G_NUM 64

#define KPAD 102400            // 800 * 128, zero-padded beyond N_NODES
#define NBLK 800
#define KC 128
#define TK 16
#define NT (KC / TK)           // 8 tiles per block

// ---------------- scratch (device globals) ----------------
__device__ int   g_cnt[N_NODES];
__device__ __align__(16) int2  g_db[N_NODES];        // {batch[i], dis[i] as int}
__device__ __align__(16) float g_xn[N_NODES * 4];    // x[i]*dis[i], w = 0
__device__ __align__(16) float g_agg3[N_NODES * 4];  // {self+sum xn, w = dis[i]}
__device__ __align__(16) float g_C[(size_t)KPAD * G_NUM];   // C[k][g]
__device__ __align__(16) float g_h1s[(size_t)KPAD * D];     // dis_k * h1r[k][f]
__device__ __align__(16) float g_T[G_NUM * D];
__device__ int   g_cntg[G_NUM];

// ---------------- helpers ----------------
__device__ __forceinline__ unsigned long long packf2(float v) {
    unsigned long long r;
    unsigned int u = __float_as_uint(v);
    asm("mov.b64 %0, {%1, %1};" : "=l"(r) : "r"(u));
    return r;
}
__device__ __forceinline__ void fma2(unsigned long long& d, unsigned long long a,
                                     unsigned long long b) {
    asm("fma.rn.f32x2 %0, %1, %2, %0;" : "+l"(d) : "l"(a), "l"(b));
}
__device__ __forceinline__ void red_add_v4(float* p, float4 v) {
    unsigned long long gp = (unsigned long long)__cvta_generic_to_global(p);
    asm volatile("red.global.add.v4.f32 [%0], {%1,%2,%3,%4};"
                 :: "l"(gp), "f"(v.x), "f"(v.y), "f"(v.z), "f"(v.w) : "memory");
}
__device__ __forceinline__ void cpa16(void* smem, const void* g) {
    unsigned s = (unsigned)__cvta_generic_to_shared(smem);
    unsigned long long ga = (unsigned long long)__cvta_generic_to_global(g);
    asm volatile("cp.async.ca.shared.global [%0], [%1], 16;" :: "r"(s), "l"(ga));
}
#define CP_COMMIT() asm volatile("cp.async.commit_group;" ::: "memory")
#define CP_WAIT0()  asm volatile("cp.async.wait_group 0;" ::: "memory")
#define CP_WAIT1()  asm volatile("cp.async.wait_group 1;" ::: "memory")

// ---------------- fused zero of small buffers (replaces 3 memsets) ----------------
__global__ void k_zero() {
    int i = blockIdx.x * blockDim.x + threadIdx.x;
    if (i < N_NODES) g_cnt[i] = 0;
    if (i < G_NUM * D) g_T[i] = 0.0f;
    if (i < G_NUM) g_cntg[i] = 0;
}

// ---------------- degree histogram (1 edge / thread) ----------------
__global__ void k_hist(const int* __restrict__ dst) {
    int e = blockIdx.x * blockDim.x + threadIdx.x;
    if (e < N_EDGES) atomicAdd(&g_cnt[dst[e]], 1);
}

// ---------------- fused init: C rows (single touch, self term) + per-node state ----------------
__global__ void k_dis_init(const float* __restrict__ x, const int* __restrict__ batch) {
    int idx = blockIdx.x * blockDim.x + threadIdx.x;   // over KPAD*16 float4 slots
    if (idx >= KPAD * 16) return;
    int node = idx >> 4;
    int slot = idx & 15;
    if (node >= N_NODES) {      // zero pad rows
        ((float4*)g_C)[idx] = make_float4(0.f, 0.f, 0.f, 0.f);
        return;
    }
    float dv = rsqrtf((float)(g_cnt[node] + 1));
    int b = batch[node];
    float4 v = make_float4(0.f, 0.f, 0.f, 0.f);
    int gbase = slot * 4;
    if (b - gbase == 0) v.x = dv;
    else if (b - gbase == 1) v.y = dv;
    else if (b - gbase == 2) v.z = dv;
    else if (b - gbase == 3) v.w = dv;
    ((float4*)g_C)[idx] = v;
    if (slot == 0) {
        g_db[node] = make_int2(b, __float_as_int(dv));
        float xa = x[node * 3 + 0] * dv;
        float xb = x[node * 3 + 1] * dv;
        float xc = x[node * 3 + 2] * dv;
        ((float4*)g_xn)[node]   = make_float4(xa, xb, xc, 0.0f);
        ((float4*)g_agg3)[node] = make_float4(xa, xb, xc, dv);   // w carries dis
        atomicAdd(&g_cntg[b], 1);
    }
}

// ---------------- per-edge (1/thread): agg3[d].xyz += xn[s];  C[s][batch[d]] += dis[d] ----------------
__global__ void k_edge(const int* __restrict__ src, const int* __restrict__ dst) {
    int e = blockIdx.x * blockDim.x + threadIdx.x;
    if (e >= N_EDGES) return;
    int s = src[e];
    int d = dst[e];
    int2 db = g_db[d];
    float disd = __int_as_float(db.y);
    float4 v = ((const float4*)g_xn)[s];          // w = 0, preserves agg3.w = dis
    red_add_v4(&g_agg3[d * 4], v);
    atomicAdd(&g_C[(size_t)s * G_NUM + db.x], disd);
}

// ---------------- h1s[k] = dis_k * relu(b1 + (agg3[k]*dis_k) @ W1)  (1 warp / node) ----------------
__global__ __launch_bounds__(256) void k_l1post(const float* __restrict__ W1,
                                                const float* __restrict__ b1) {
    int node = (int)((blockIdx.x * 256u + threadIdx.x) >> 5);
    if (node >= KPAD) return;
    int c4 = threadIdx.x & 31;
    float4 r = make_float4(0.f, 0.f, 0.f, 0.f);
    if (node < N_NODES) {
        float4 w0 = __ldg((const float4*)W1 + c4);
        float4 w1 = __ldg((const float4*)(W1 + D) + c4);
        float4 w2 = __ldg((const float4*)(W1 + 2 * D) + c4);
        float4 bv = __ldg((const float4*)b1 + c4);
        float4 ag = ((const float4*)g_agg3)[node];
        float dv = ag.w;
        float a0 = ag.x * dv, a1 = ag.y * dv, a2 = ag.z * dv;
        r.x = dv * fmaxf(bv.x + a0 * w0.x + a1 * w1.x + a2 * w2.x, 0.0f);
        r.y = dv * fmaxf(bv.y + a0 * w0.y + a1 * w1.y + a2 * w2.y, 0.0f);
        r.z = dv * fmaxf(bv.z + a0 * w0.z + a1 * w1.z + a2 * w2.z, 0.0f);
        r.w = dv * fmaxf(bv.w + a0 * w0.w + a1 * w1.w + a2 * w2.w, 0.0f);
    }
    ((float4*)g_h1s)[(size_t)node * 32 + c4] = r;
}

// ---------------- pure-copy pipelined tall GEMM (128 thr, 8g x 8f, TK=16, 5 blocks/SM) ----------------
// g_T[g][f] += sum_k C[k][g] * h1s[k][f]
__global__ __launch_bounds__(128, 5) void k_gemmS() {
    extern __shared__ __align__(16) float smem[];
    float* sC = smem;                        // [2][TK*64]    8 KB
    float* sh = smem + 2 * TK * G_NUM;       // [2][TK*128]  16 KB
    int tid = threadIdx.x;
    int g0 = (tid >> 4) * 8;
    int f0 = (tid & 15) * 8;
    int kbase = blockIdx.x * KC;

    auto issue = [&](int buf, int k0) {
        float* dC = sC + buf * TK * G_NUM;
        const float4* gc = (const float4*)(g_C + (size_t)k0 * G_NUM);
        for (int i = tid; i < TK * G_NUM / 4; i += 128)
            cpa16(&((float4*)dC)[i], &gc[i]);
        float* dh = sh + buf * TK * D;
        const float4* gh = (const float4*)(g_h1s + (size_t)k0 * D);
        for (int i = tid; i < TK * D / 4; i += 128)
            cpa16(&((float4*)dh)[i], &gh[i]);
        CP_COMMIT();
    };

    unsigned long long acc[8][4];
#pragma unroll
    for (int i = 0; i < 8; i++)
#pragma unroll
        for (int p = 0; p < 4; p++) acc[i][p] = 0ULL;

    issue(0, kbase);

#pragma unroll 1
    for (int t = 0; t < NT; t++) {
        int cur = t & 1;
        if (t + 1 < NT) { issue(cur ^ 1, kbase + (t + 1) * TK); CP_WAIT1(); }
        else            { CP_WAIT0(); }
        __syncthreads();

        const float* tC = sC + cur * TK * G_NUM;
        const float* th = sh + cur * TK * D;
#pragma unroll
        for (int kk = 0; kk < TK; kk++) {
            float4 ca = *(const float4*)(tC + kk * G_NUM + g0);
            float4 cb = *(const float4*)(tC + kk * G_NUM + g0 + 4);
            ulonglong2 h01 = *(const ulonglong2*)(th + kk * D + f0);
            ulonglong2 h23 = *(const ulonglong2*)(th + kk * D + f0 + 4);
            unsigned long long hp[4] = {h01.x, h01.y, h23.x, h23.y};
            unsigned long long cp[8];
            cp[0] = packf2(ca.x); cp[1] = packf2(ca.y);
            cp[2] = packf2(ca.z); cp[3] = packf2(ca.w);
            cp[4] = packf2(cb.x); cp[5] = packf2(cb.y);
            cp[6] = packf2(cb.z); cp[7] = packf2(cb.w);
#pragma unroll
            for (int i = 0; i < 8; i++)
#pragma unroll
                for (int p = 0; p < 4; p++) fma2(acc[i][p], cp[i], hp[p]);
        }
        __syncthreads();
    }

    // epilogue: atomic reduce into g_T
#pragma unroll
    for (int i = 0; i < 8; i++) {
        float2 v0 = *(float2*)&acc[i][0];
        float2 v1 = *(float2*)&acc[i][1];
        float2 v2 = *(float2*)&acc[i][2];
        float2 v3 = *(float2*)&acc[i][3];
        red_add_v4(&g_T[(g0 + i) * D + f0],     make_float4(v0.x, v0.y, v1.x, v1.y));
        red_add_v4(&g_T[(g0 + i) * D + f0 + 4], make_float4(v2.x, v2.y, v3.x, v3.y));
    }
}

// ---------------- mean + @W2+b2 + @Wf+bf  (block per graph, 512 thr) ----------------
__global__ __launch_bounds__(512) void k_pwq(const float* __restrict__ W2,
                                             const float* __restrict__ b2,
                                             const float* __restrict__ Wf,
                                             const float* __restrict__ bf,
                                             float* __restrict__ q) {
    __shared__ float sT[D];
    __shared__ float sge[D];
    int g = blockIdx.x;
    int tid = threadIdx.x;    // 512

    if (tid < D) {
        float cnt = fmaxf((float)g_cntg[g], 1.0f);
        sT[tid] = g_T[g * D + tid] / cnt;
    }
    __syncthreads();

    if (tid < D) {
        float acc = b2[tid];
#pragma unroll 16
        for (int k = 0; k < D; k++) acc += sT[k] * W2[k * D + tid];
        sge[tid] = acc;
    }
    __syncthreads();

    {
        int a = tid;            // 512 threads == A_DIM outputs
        float acc = bf[a];
#pragma unroll 16
        for (int k = 0; k < D; k++) acc += sge[k] * Wf[k * A_DIM + a];
        q[g * A_DIM + a] = acc;
    }
}

// ---------------- launch ----------------
extern "C" void kernel_launch(void* const* d_in, const int* in_sizes, int n_in,
                              void* d_out, int out_size) {
    const float* x     = (const float*)d_in[0];
    const int*   ei    = (const int*)  d_in[1];
    const int*   batch = (const int*)  d_in[2];
    const float* W1    = (const float*)d_in[3];
    const float* b1    = (const float*)d_in[4];
    const float* W2    = (const float*)d_in[5];
    const float* b2    = (const float*)d_in[6];
    const float* Wf    = (const float*)d_in[7];
    const float* bf    = (const float*)d_in[8];
    float* q = (float*)d_out;

    const int* src = ei;
    const int* dst = ei + N_EDGES;

    k_zero<<<(N_NODES + 255) / 256, 256>>>();
    k_hist<<<(N_EDGES + 255) / 256, 256>>>(dst);
    k_dis_init<<<(KPAD * 16 + 255) / 256, 256>>>(x, batch);
    k_edge<<<(N_EDGES + 255) / 256, 256>>>(src, dst);
    k_l1post<<<(KPAD * 32 + 255) / 256, 256>>>(W1, b1);

    int gemm_smem = (2 * TK * G_NUM + 2 * TK * D) * (int)sizeof(float);   // 24576
    cudaFuncSetAttribute(k_gemmS, cudaFuncAttributeMaxDynamicSharedMemorySize, gemm_smem);
    k_gemmS<<<NBLK, 128, gemm_smem>>>();

    k_pwq<<<G_NUM, 512>>>(W2, b2, Wf, bf, q);
}

// round 15
// speedup vs baseline: 1.0093x; 1.0093x over previous
#include <cuda_runtime.h>
#include <cstdint>

#define N_NODES 100000
#define N_EDGES 1600000
#define D 128
#define A_DIM 512
#define G_NUM 64

// tall GEMM config: NBLK * KC == N_NODES exactly
#define NBLK 800
#define KC 125
#define TK 25
#define NT (KC / TK)   // 5 tiles per block

// ---------------- scratch (device globals) ----------------
__device__ int   g_cnt[N_NODES];
__device__ __align__(16) int2  g_db[N_NODES];        // {batch[i], dis[i] as int}
__device__ __align__(16) float g_xn[N_NODES * 4];    // x[i]*dis[i], w = 0
__device__ __align__(16) float g_agg3[N_NODES * 4];  // {self+sum xn, w = dis[i]}
__device__ __align__(16) float g_C[(size_t)N_NODES * G_NUM]; // Craw[k][g]
__device__ __align__(16) float g_T[G_NUM * D];
__device__ int   g_cntg[G_NUM];

// ---------------- helpers ----------------
__device__ __forceinline__ unsigned long long packf2(float v) {
    unsigned long long r;
    unsigned int u = __float_as_uint(v);
    asm("mov.b64 %0, {%1, %1};" : "=l"(r) : "r"(u));
    return r;
}
__device__ __forceinline__ void fma2(unsigned long long& d, unsigned long long a,
                                     unsigned long long b) {
    asm("fma.rn.f32x2 %0, %1, %2, %0;" : "+l"(d) : "l"(a), "l"(b));
}
__device__ __forceinline__ void red_add_v4(float* p, float4 v) {
    unsigned long long gp = (unsigned long long)__cvta_generic_to_global(p);
    asm volatile("red.global.add.v4.f32 [%0], {%1,%2,%3,%4};"
                 :: "l"(gp), "f"(v.x), "f"(v.y), "f"(v.z), "f"(v.w) : "memory");
}

// ---------------- degree histogram + zero small buffers ----------------
__global__ void k_hist(const int* __restrict__ dst) {
    int e = blockIdx.x * blockDim.x + threadIdx.x;
    if (e < G_NUM * D) g_T[e] = 0.0f;
    if (e < G_NUM) g_cntg[e] = 0;
    if (e < N_EDGES) atomicAdd(&g_cnt[dst[e]], 1);
}

// ---------------- fused init: C rows (single touch, self term) + per-node state ----------------
__global__ void k_dis_init(const float* __restrict__ x, const int* __restrict__ batch) {
    int idx = blockIdx.x * blockDim.x + threadIdx.x;   // over N_NODES*16 float4 slots
    if (idx >= N_NODES * 16) return;
    int node = idx >> 4;
    int slot = idx & 15;
    float dv = rsqrtf((float)(g_cnt[node] + 1));
    int b = batch[node];
    float4 v = make_float4(0.f, 0.f, 0.f, 0.f);
    int gbase = slot * 4;
    if (b - gbase == 0) v.x = dv;
    else if (b - gbase == 1) v.y = dv;
    else if (b - gbase == 2) v.z = dv;
    else if (b - gbase == 3) v.w = dv;
    ((float4*)g_C)[idx] = v;
    if (slot == 0) {
        g_db[node] = make_int2(b, __float_as_int(dv));
        float xa = x[node * 3 + 0] * dv;
        float xb = x[node * 3 + 1] * dv;
        float xc = x[node * 3 + 2] * dv;
        ((float4*)g_xn)[node]   = make_float4(xa, xb, xc, 0.0f);
        ((float4*)g_agg3)[node] = make_float4(xa, xb, xc, dv);   // w carries dis
        atomicAdd(&g_cntg[b], 1);
    }
}

// ---------------- per-edge: agg3[d].xyz += xn[s];  Craw[s][batch[d]] += dis[d] ----------------
__global__ void k_edge(const int* __restrict__ src, const int* __restrict__ dst) {
    int e = blockIdx.x * blockDim.x + threadIdx.x;
    if (e >= N_EDGES) return;
    int s = src[e];
    int d = dst[e];
    int2 db = g_db[d];
    float disd = __int_as_float(db.y);
    float4 v = ((const float4*)g_xn)[s];          // w = 0, preserves agg3.w = dis
    red_add_v4(&g_agg3[d * 4], v);
    atomicAdd(&g_C[(size_t)s * G_NUM + db.x], disd);
}

// ---------------- fused tall GEMM with PRE-PACKED C (128 thr, 8g x 8f, 5 blocks/SM) ----------------
// g_T[g][f] += sum_k Craw[k][g] * (dis_k * h1r[k][f])
// h1r[k][f] = relu(b1[f] + (agg3[k]*dis_k) @ W1); dis_k = agg3[k].w.
// C staged as duplicated f32 pairs -> inner loop has zero pack MOVs.
__global__ __launch_bounds__(128, 5) void k_gemmS(const float* __restrict__ W1,
                                                  const float* __restrict__ b1) {
    __shared__ __align__(16) unsigned long long sCp[TK * G_NUM];  // 12.8 KB packed
    __shared__ __align__(16) float sh[TK * D];                    // 12.8 KB
    __shared__ __align__(16) float sW[3 * D];
    __shared__ __align__(16) float sb[D];
    int tid = threadIdx.x;
    int g0 = (tid >> 4) * 8;        // 8 groups of 8 graphs
    int f0 = (tid & 15) * 8;        // 16 groups of 8 features
    int kbase = blockIdx.x * KC;

    if (tid < 96) ((float4*)sW)[tid] = ((const float4*)W1)[tid];
    if (tid >= 96 && tid < 128) ((float4*)sb)[tid - 96] = ((const float4*)b1)[tid - 96];
    __syncthreads();

    unsigned long long acc[8][4];
#pragma unroll
    for (int i = 0; i < 8; i++)
#pragma unroll
        for (int p = 0; p < 4; p++) acc[i][p] = 0ULL;

#pragma unroll 1
    for (int t = 0; t < NT; t++) {
        int k0 = kbase + t * TK;

        // stage C pre-packed: float4 -> two ulonglong2 (each value duplicated)
        const float4* Cg = (const float4*)(g_C + (size_t)k0 * G_NUM);
        for (int i = tid; i < TK * G_NUM / 4; i += 128) {
            float4 c = Cg[i];
            ulonglong2 pa, pb;
            pa.x = packf2(c.x); pa.y = packf2(c.y);
            pb.x = packf2(c.z); pb.y = packf2(c.w);
            ((ulonglong2*)sCp)[i * 2]     = pa;
            ((ulonglong2*)sCp)[i * 2 + 1] = pb;
        }
        // stage h computed on the fly (fused layer-1 epilogue, dis folded in)
        for (int i = tid; i < TK * D / 4; i += 128) {
            int r = i >> 5;                 // 32 float4 per h row
            int c = (i & 31) * 4;
            float4 ag = ((const float4*)g_agg3)[k0 + r];
            float dv = ag.w;
            float a0 = ag.x * dv, a1 = ag.y * dv, a2 = ag.z * dv;
            float4 w0 = *(const float4*)(sW + 0 * D + c);
            float4 w1 = *(const float4*)(sW + 1 * D + c);
            float4 w2 = *(const float4*)(sW + 2 * D + c);
            float4 bv = *(const float4*)(sb + c);
            float4 hv;
            hv.x = dv * fmaxf(bv.x + a0 * w0.x + a1 * w1.x + a2 * w2.x, 0.0f);
            hv.y = dv * fmaxf(bv.y + a0 * w0.y + a1 * w1.y + a2 * w2.y, 0.0f);
            hv.z = dv * fmaxf(bv.z + a0 * w0.z + a1 * w1.z + a2 * w2.z, 0.0f);
            hv.w = dv * fmaxf(bv.w + a0 * w0.w + a1 * w1.w + a2 * w2.w, 0.0f);
            ((float4*)sh)[i] = hv;
        }
        __syncthreads();

#pragma unroll
        for (int kk = 0; kk < TK; kk++) {
            const ulonglong2* cpp = (const ulonglong2*)(sCp + kk * G_NUM + g0);
            ulonglong2 c01 = cpp[0];
            ulonglong2 c23 = cpp[1];
            ulonglong2 c45 = cpp[2];
            ulonglong2 c67 = cpp[3];
            ulonglong2 h01 = *(const ulonglong2*)(sh + kk * D + f0);
            ulonglong2 h23 = *(const ulonglong2*)(sh + kk * D + f0 + 4);
            unsigned long long hp[4] = {h01.x, h01.y, h23.x, h23.y};
            unsigned long long cp[8] = {c01.x, c01.y, c23.x, c23.y,
                                        c45.x, c45.y, c67.x, c67.y};
#pragma unroll
            for (int i = 0; i < 8; i++)
#pragma unroll
                for (int p = 0; p < 4; p++) fma2(acc[i][p], cp[i], hp[p]);
        }
        __syncthreads();
    }

    // epilogue: atomic reduce into g_T
#pragma unroll
    for (int i = 0; i < 8; i++) {
        float2 v0 = *(float2*)&acc[i][0];
        float2 v1 = *(float2*)&acc[i][1];
        float2 v2 = *(float2*)&acc[i][2];
        float2 v3 = *(float2*)&acc[i][3];
        red_add_v4(&g_T[(g0 + i) * D + f0],     make_float4(v0.x, v0.y, v1.x, v1.y));
        red_add_v4(&g_T[(g0 + i) * D + f0 + 4], make_float4(v2.x, v2.y, v3.x, v3.y));
    }
}

// ---------------- mean + @W2+b2 + @Wf+bf  (block per graph, 512 thr) ----------------
__global__ __launch_bounds__(512) void k_pwq(const float* __restrict__ W2,
                                             const float* __restrict__ b2,
                                             const float* __restrict__ Wf,
                                             const float* __restrict__ bf,
                                             float* __restrict__ q) {
    __shared__ float sT[D];
    __shared__ float sge[D];
    int g = blockIdx.x;
    int tid = threadIdx.x;    // 512

    if (tid < D) {
        float cnt = fmaxf((float)g_cntg[g], 1.0f);
        sT[tid] = g_T[g * D + tid] / cnt;
    }
    __syncthreads();

    if (tid < D) {
        float acc = b2[tid];
#pragma unroll 16
        for (int k = 0; k < D; k++) acc += sT[k] * W2[k * D + tid];
        sge[tid] = acc;
    }
    __syncthreads();

    {
        int a = tid;            // 512 threads == A_DIM outputs
        float acc = bf[a];
#pragma unroll 16
        for (int k = 0; k < D; k++) acc += sge[k] * Wf[k * A_DIM + a];
        q[g * A_DIM + a] = acc;
    }
}

// ---------------- launch ----------------
extern "C" void kernel_launch(void* const* d_in, const int* in_sizes, int n_in,
                              void* d_out, int out_size) {
    const float* x     = (const float*)d_in[0];
    const int*   ei    = (const int*)  d_in[1];
    const int*   batch = (const int*)  d_in[2];
    const float* W1    = (const float*)d_in[3];
    const float* b1    = (const float*)d_in[4];
    const float* W2    = (const float*)d_in[5];
    const float* b2    = (const float*)d_in[6];
    const float* Wf    = (const float*)d_in[7];
    const float* bf    = (const float*)d_in[8];
    float* q = (float*)d_out;

    const int* src = ei;
    const int* dst = ei + N_EDGES;

    void* pc;
    cudaGetSymbolAddress(&pc, g_cnt);
    cudaMemsetAsync(pc, 0, N_NODES * sizeof(int));

    k_hist<<<(N_EDGES + 255) / 256, 256>>>(dst);
    k_dis_init<<<(N_NODES * 16 + 255) / 256, 256>>>(x, batch);
    k_edge<<<(N_EDGES + 255) / 256, 256>>>(src, dst);
    k_gemmS<<<NBLK, 128>>>(W1, b1);
    k_pwq<<<G_NUM, 512>>>(W2, b2, Wf, bf, q);
}

// round 16
// speedup vs baseline: 1.1882x; 1.1773x over previous
#include <cuda_runtime.h>
#include <cuda_bf16.h>
#include <cstdint>

#define N_NODES 100000
#define N_EDGES 1600000
#define D 128
#define A_DIM 512
#define G_NUM 64

#define NCHUNK 6250          // 100000 / 16
#define MGRID 625            // grid for k_mma; 10 chunks per CTA

// ---------------- scratch (device globals) ----------------
__device__ int   g_cnt[N_NODES];
__device__ __align__(16) int2  g_db[N_NODES];        // {batch[i], dis[i] as int}
__device__ __align__(16) float g_xn[N_NODES * 4];    // x[i]*dis[i], w = 0
__device__ __align__(16) float g_agg3[N_NODES * 4];  // {self+sum xn, w = dis[i]}
__device__ __align__(16) float g_C[(size_t)N_NODES * G_NUM]; // C[k][g], g contiguous
__device__ __align__(16) float g_T[G_NUM * D];
__device__ int   g_cntg[G_NUM];

// ---------------- helpers ----------------
__device__ __forceinline__ void red_add_v4(float* p, float4 v) {
    unsigned long long gp = (unsigned long long)__cvta_generic_to_global(p);
    asm volatile("red.global.add.v4.f32 [%0], {%1,%2,%3,%4};"
                 :: "l"(gp), "f"(v.x), "f"(v.y), "f"(v.z), "f"(v.w) : "memory");
}
__device__ __forceinline__ void red_add_v2(float* p, float a, float b) {
    unsigned long long gp = (unsigned long long)__cvta_generic_to_global(p);
    asm volatile("red.global.add.v2.f32 [%0], {%1,%2};"
                 :: "l"(gp), "f"(a), "f"(b) : "memory");
}
__device__ __forceinline__ uint32_t smem_u32(const void* p) {
    uint32_t a;
    asm("{ .reg .u64 t; cvta.to.shared.u64 t, %1; cvt.u32.u64 %0, t; }"
        : "=r"(a) : "l"(p));
    return a;
}

// ---------------- degree histogram + zero small buffers ----------------
__global__ void k_hist(const int* __restrict__ dst) {
    int e = blockIdx.x * blockDim.x + threadIdx.x;
    if (e < G_NUM * D) g_T[e] = 0.0f;
    if (e < G_NUM) g_cntg[e] = 0;
    if (e < N_EDGES) atomicAdd(&g_cnt[dst[e]], 1);
}

// ---------------- fused init: C rows (single touch, self term) + per-node state ----------------
__global__ void k_dis_init(const float* __restrict__ x, const int* __restrict__ batch) {
    int idx = blockIdx.x * blockDim.x + threadIdx.x;   // over N_NODES*16 float4 slots
    if (idx >= N_NODES * 16) return;
    int node = idx >> 4;
    int slot = idx & 15;
    float dv = rsqrtf((float)(g_cnt[node] + 1));
    int b = batch[node];
    float4 v = make_float4(0.f, 0.f, 0.f, 0.f);
    int gbase = slot * 4;
    if (b - gbase == 0) v.x = dv;
    else if (b - gbase == 1) v.y = dv;
    else if (b - gbase == 2) v.z = dv;
    else if (b - gbase == 3) v.w = dv;
    ((float4*)g_C)[idx] = v;
    if (slot == 0) {
        g_db[node] = make_int2(b, __float_as_int(dv));
        float xa = x[node * 3 + 0] * dv;
        float xb = x[node * 3 + 1] * dv;
        float xc = x[node * 3 + 2] * dv;
        ((float4*)g_xn)[node]   = make_float4(xa, xb, xc, 0.0f);
        ((float4*)g_agg3)[node] = make_float4(xa, xb, xc, dv);   // w carries dis
        atomicAdd(&g_cntg[b], 1);
    }
}

// ---------------- per-edge: agg3[d].xyz += xn[s];  C[s][batch[d]] += dis[d] ----------------
__global__ void k_edge(const int* __restrict__ src, const int* __restrict__ dst) {
    int e = blockIdx.x * blockDim.x + threadIdx.x;
    if (e >= N_EDGES) return;
    int s = src[e];
    int d = dst[e];
    int2 db = g_db[d];
    float disd = __int_as_float(db.y);
    float4 v = ((const float4*)g_xn)[s];          // w = 0, preserves agg3.w = dis
    red_add_v4(&g_agg3[d * 4], v);
    atomicAdd(&g_C[(size_t)s * G_NUM + db.x], disd);
}

// ---------------- tensor-core tall GEMM (mma.sync m16n8k16 bf16) ----------------
// T[g][f] += sum_k C[k][g] * h1s[k][f];  h1s fused from agg3 during B staging.
// A = C^T [64g x 16k] bf16 in smem (24-elt padded rows); B = h [16k x 128f] bf16 (136-elt rows).
__global__ __launch_bounds__(128) void k_mma(const float* __restrict__ W1,
                                             const float* __restrict__ b1) {
    __shared__ __align__(16) float sW[3 * D];
    __shared__ __align__(16) float sb[D];
    __shared__ __align__(16) __nv_bfloat16 sA[64 * 24];
    __shared__ __align__(16) __nv_bfloat16 sB[16 * 136];
    int tid = threadIdx.x;
    int lane = tid & 31, wid = tid >> 5;

    if (tid < 96) ((float4*)sW)[tid] = ((const float4*)W1)[tid];
    else          ((float4*)sb)[tid - 96] = ((const float4*)b1)[tid - 96];

    float acc[16][4];
#pragma unroll
    for (int i = 0; i < 16; i++)
#pragma unroll
        for (int j = 0; j < 4; j++) acc[i][j] = 0.0f;

    // ldmatrix addresses (fixed per thread; smem tiles are reused each chunk)
    int grp = lane >> 3, i8 = lane & 7;
    int g0 = wid * 16;
    uint32_t aAddr = smem_u32(sA) +
        (uint32_t)(((g0 + i8 + ((grp & 1) ? 8 : 0)) * 24 + ((grp & 2) ? 8 : 0)) * 2);
    uint32_t bAddr0 = smem_u32(sB) +
        (uint32_t)(((i8 + ((grp & 1) ? 8 : 0)) * 136 + ((grp & 2) ? 8 : 0)) * 2);

    // staging roles
    int g4  = tid >> 3;            // 0..15 -> g range g4*4..+4  (A staging)
    int kk2 = (tid & 7) * 2;       // 0..14 even                  (A staging)
    int kkB = tid >> 3;            // 0..15 row                   (B staging)
    int fs  = (tid & 7) * 16;      // 0..112 f-segment            (B staging)

    __syncthreads();   // sW/sb visible to all

    for (int chunk = blockIdx.x; chunk < NCHUNK; chunk += MGRID) {
        int k0 = chunk * 16;

        // ---- stage A: transpose C[16k x 64g] fp32 -> sA[64g x 16k] bf16 ----
        {
            const float* r0 = g_C + (size_t)(k0 + kk2) * G_NUM + g4 * 4;
            float4 c0 = *(const float4*)r0;
            float4 c1 = *(const float4*)(r0 + G_NUM);
            __nv_bfloat16* base = sA + (g4 * 4) * 24 + kk2;
            *(__nv_bfloat162*)(base + 0 * 24) = __floats2bfloat162_rn(c0.x, c1.x);
            *(__nv_bfloat162*)(base + 1 * 24) = __floats2bfloat162_rn(c0.y, c1.y);
            *(__nv_bfloat162*)(base + 2 * 24) = __floats2bfloat162_rn(c0.z, c1.z);
            *(__nv_bfloat162*)(base + 3 * 24) = __floats2bfloat162_rn(c0.w, c1.w);
        }
        // ---- stage B: h row kkB, f in [fs, fs+16)  (fused layer-1 epilogue) ----
        {
            float4 ag = ((const float4*)g_agg3)[k0 + kkB];
            float dv = ag.w;
            float a0 = ag.x * dv, a1 = ag.y * dv, a2 = ag.z * dv;
            uint32_t outp[8];
#pragma unroll
            for (int m = 0; m < 4; m++) {
                int f = fs + m * 4;
                float4 w0 = *(const float4*)(sW + f);
                float4 w1 = *(const float4*)(sW + D + f);
                float4 w2 = *(const float4*)(sW + 2 * D + f);
                float4 bv = *(const float4*)(sb + f);
                float h0 = dv * fmaxf(bv.x + a0 * w0.x + a1 * w1.x + a2 * w2.x, 0.f);
                float h1 = dv * fmaxf(bv.y + a0 * w0.y + a1 * w1.y + a2 * w2.y, 0.f);
                float h2 = dv * fmaxf(bv.z + a0 * w0.z + a1 * w1.z + a2 * w2.z, 0.f);
                float h3 = dv * fmaxf(bv.w + a0 * w0.w + a1 * w1.w + a2 * w2.w, 0.f);
                __nv_bfloat162 pa = __floats2bfloat162_rn(h0, h1);
                __nv_bfloat162 pb = __floats2bfloat162_rn(h2, h3);
                outp[m * 2]     = *(uint32_t*)&pa;
                outp[m * 2 + 1] = *(uint32_t*)&pb;
            }
            *(uint4*)(sB + kkB * 136 + fs)     = make_uint4(outp[0], outp[1], outp[2], outp[3]);
            *(uint4*)(sB + kkB * 136 + fs + 8) = make_uint4(outp[4], outp[5], outp[6], outp[7]);
        }
        __syncthreads();

        // ---- MMA: A-frag once, 8x B ldmatrix (2 n-tiles each), 16 mma ----
        uint32_t a[4];
        asm volatile("ldmatrix.sync.aligned.m8n8.x4.shared.b16 {%0,%1,%2,%3}, [%4];"
                     : "=r"(a[0]), "=r"(a[1]), "=r"(a[2]), "=r"(a[3]) : "r"(aAddr));
#pragma unroll
        for (int nt = 0; nt < 16; nt += 2) {
            uint32_t b[4];
            asm volatile("ldmatrix.sync.aligned.m8n8.x4.trans.shared.b16 {%0,%1,%2,%3}, [%4];"
                         : "=r"(b[0]), "=r"(b[1]), "=r"(b[2]), "=r"(b[3])
                         : "r"(bAddr0 + nt * 16));
            asm volatile("mma.sync.aligned.m16n8k16.row.col.f32.bf16.bf16.f32 "
                         "{%0,%1,%2,%3}, {%4,%5,%6,%7}, {%8,%9}, {%0,%1,%2,%3};"
                         : "+f"(acc[nt][0]), "+f"(acc[nt][1]), "+f"(acc[nt][2]), "+f"(acc[nt][3])
                         : "r"(a[0]), "r"(a[1]), "r"(a[2]), "r"(a[3]), "r"(b[0]), "r"(b[1]));
            asm volatile("mma.sync.aligned.m16n8k16.row.col.f32.bf16.bf16.f32 "
                         "{%0,%1,%2,%3}, {%4,%5,%6,%7}, {%8,%9}, {%0,%1,%2,%3};"
                         : "+f"(acc[nt+1][0]), "+f"(acc[nt+1][1]), "+f"(acc[nt+1][2]), "+f"(acc[nt+1][3])
                         : "r"(a[0]), "r"(a[1]), "r"(a[2]), "r"(a[3]), "r"(b[2]), "r"(b[3]));
        }
        __syncthreads();
    }

    // ---- epilogue: red accumulators into g_T ----
    int gRow = wid * 16 + (lane >> 2);
    int fCol = (lane & 3) * 2;
#pragma unroll
    for (int nt = 0; nt < 16; nt++) {
        red_add_v2(&g_T[gRow * D + nt * 8 + fCol],       acc[nt][0], acc[nt][1]);
        red_add_v2(&g_T[(gRow + 8) * D + nt * 8 + fCol], acc[nt][2], acc[nt][3]);
    }
}

// ---------------- mean + @W2+b2 + @Wf+bf  (block per graph, 512 thr) ----------------
__global__ __launch_bounds__(512) void k_pwq(const float* __restrict__ W2,
                                             const float* __restrict__ b2,
                                             const float* __restrict__ Wf,
                                             const float* __restrict__ bf,
                                             float* __restrict__ q) {
    __shared__ float sT[D];
    __shared__ float sge[D];
    int g = blockIdx.x;
    int tid = threadIdx.x;    // 512

    if (tid < D) {
        float cnt = fmaxf((float)g_cntg[g], 1.0f);
        sT[tid] = g_T[g * D + tid] / cnt;
    }
    __syncthreads();

    if (tid < D) {
        float acc = b2[tid];
#pragma unroll 16
        for (int k = 0; k < D; k++) acc += sT[k] * W2[k * D + tid];
        sge[tid] = acc;
    }
    __syncthreads();

    {
        int a = tid;            // 512 threads == A_DIM outputs
        float acc = bf[a];
#pragma unroll 16
        for (int k = 0; k < D; k++) acc += sge[k] * Wf[k * A_DIM + a];
        q[g * A_DIM + a] = acc;
    }
}

// ---------------- launch ----------------
extern "C" void kernel_launch(void* const* d_in, const int* in_sizes, int n_in,
                              void* d_out, int out_size) {
    const float* x     = (const float*)d_in[0];
    const int*   ei    = (const int*)  d_in[1];
    const int*   batch = (const int*)  d_in[2];
    const float* W1    = (const float*)d_in[3];
    const float* b1    = (const float*)d_in[4];
    const float* W2    = (const float*)d_in[5];
    const float* b2    = (const float*)d_in[6];
    const float* Wf    = (const float*)d_in[7];
    const float* bf    = (const float*)d_in[8];
    float* q = (float*)d_out;

    const int* src = ei;
    const int* dst = ei + N_EDGES;

    void* pc;
    cudaGetSymbolAddress(&pc, g_cnt);
    cudaMemsetAsync(pc, 0, N_NODES * sizeof(int));

    k_hist<<<(N_EDGES + 255) / 256, 256>>>(dst);
    k_dis_init<<<(N_NODES * 16 + 255) / 256, 256>>>(x, batch);
    k_edge<<<(N_EDGES + 255) / 256, 256>>>(src, dst);
    k_mma<<<MGRID, 128>>>(W1, b1);
    k_pwq<<<G_NUM, 512>>>(W2, b2, Wf, bf, q);
}

// round 17
// speedup vs baseline: 1.2060x; 1.0150x over previous
#include <cuda_runtime.h>
#include <cuda_bf16.h>
#include <cstdint>

#define N_NODES 100000
#define N_EDGES 1600000
#define D 128
#define A_DIM 512
#define G_NUM 64

#define NCHUNK32 3125        // 100000 / 32
#define MGRID 625            // 5 chunks per CTA exactly

// ---------------- scratch (device globals) ----------------
__device__ int   g_cnt[N_NODES];
__device__ __align__(16) int2  g_db[N_NODES];        // {batch[i], dis[i] as int}
__device__ __align__(16) float g_xn[N_NODES * 4];    // x[i]*dis[i], w = 0
__device__ __align__(16) float g_agg3[N_NODES * 4];  // {self+sum xn, w = dis[i]}
__device__ __align__(16) float g_C[(size_t)N_NODES * G_NUM]; // C[k][g], g contiguous
__device__ __align__(16) float g_T[G_NUM * D];
__device__ int   g_cntg[G_NUM];

// ---------------- helpers ----------------
__device__ __forceinline__ void red_add_v4(float* p, float4 v) {
    unsigned long long gp = (unsigned long long)__cvta_generic_to_global(p);
    asm volatile("red.global.add.v4.f32 [%0], {%1,%2,%3,%4};"
                 :: "l"(gp), "f"(v.x), "f"(v.y), "f"(v.z), "f"(v.w) : "memory");
}
__device__ __forceinline__ void red_add_v2(float* p, float a, float b) {
    unsigned long long gp = (unsigned long long)__cvta_generic_to_global(p);
    asm volatile("red.global.add.v2.f32 [%0], {%1,%2};"
                 :: "l"(gp), "f"(a), "f"(b) : "memory");
}
__device__ __forceinline__ uint32_t smem_u32(const void* p) {
    uint32_t a;
    asm("{ .reg .u64 t; cvta.to.shared.u64 t, %1; cvt.u32.u64 %0, t; }"
        : "=r"(a) : "l"(p));
    return a;
}

// ---------------- degree histogram + zero small buffers ----------------
__global__ void k_hist(const int* __restrict__ dst) {
    int e = blockIdx.x * blockDim.x + threadIdx.x;
    if (e < G_NUM * D) g_T[e] = 0.0f;
    if (e < G_NUM) g_cntg[e] = 0;
    if (e < N_EDGES) atomicAdd(&g_cnt[dst[e]], 1);
}

// ---------------- fused init: C rows (single touch, self term) + per-node state ----------------
__global__ void k_dis_init(const float* __restrict__ x, const int* __restrict__ batch) {
    int idx = blockIdx.x * blockDim.x + threadIdx.x;   // over N_NODES*16 float4 slots
    if (idx >= N_NODES * 16) return;
    int node = idx >> 4;
    int slot = idx & 15;
    float dv = rsqrtf((float)(g_cnt[node] + 1));
    int b = batch[node];
    float4 v = make_float4(0.f, 0.f, 0.f, 0.f);
    int gbase = slot * 4;
    if (b - gbase == 0) v.x = dv;
    else if (b - gbase == 1) v.y = dv;
    else if (b - gbase == 2) v.z = dv;
    else if (b - gbase == 3) v.w = dv;
    ((float4*)g_C)[idx] = v;
    if (slot == 0) {
        g_db[node] = make_int2(b, __float_as_int(dv));
        float xa = x[node * 3 + 0] * dv;
        float xb = x[node * 3 + 1] * dv;
        float xc = x[node * 3 + 2] * dv;
        ((float4*)g_xn)[node]   = make_float4(xa, xb, xc, 0.0f);
        ((float4*)g_agg3)[node] = make_float4(xa, xb, xc, dv);   // w carries dis
        atomicAdd(&g_cntg[b], 1);
    }
}

// ---------------- per-edge: agg3[d].xyz += xn[s];  C[s][batch[d]] += dis[d] ----------------
__global__ void k_edge(const int* __restrict__ src, const int* __restrict__ dst) {
    int e = blockIdx.x * blockDim.x + threadIdx.x;
    if (e >= N_EDGES) return;
    int s = src[e];
    int d = dst[e];
    int2 db = g_db[d];
    float disd = __int_as_float(db.y);
    float4 v = ((const float4*)g_xn)[s];          // w = 0, preserves agg3.w = dis
    red_add_v4(&g_agg3[d * 4], v);
    atomicAdd(&g_C[(size_t)s * G_NUM + db.x], disd);
}

// ---------------- tensor-core tall GEMM, double-buffered, 8 warps ----------------
// T[g][f] += sum_k C[k][g] * h1s[k][f];  h1s fused from agg3 during B staging.
// Warp w: g-range (w&3)*16, f-half (w>>2)*64.  K=32 per chunk, 2 k16 steps.
__global__ __launch_bounds__(256) void k_mma(const float* __restrict__ W1,
                                             const float* __restrict__ b1) {
    __shared__ __align__(16) float sW[3 * D];
    __shared__ __align__(16) float sb[D];
    __shared__ __align__(16) __nv_bfloat16 sA[2][64 * 40];   // 32k + 8 pad per row
    __shared__ __align__(16) __nv_bfloat16 sB[2][32 * 136];  // 128f + 8 pad per row
    int tid = threadIdx.x;
    int lane = tid & 31, wid = tid >> 5;

    if (tid < 96) ((float4*)sW)[tid] = ((const float4*)W1)[tid];
    else if (tid < 128) ((float4*)sb)[tid - 96] = ((const float4*)b1)[tid - 96];

    float acc[8][4];
#pragma unroll
    for (int i = 0; i < 8; i++)
#pragma unroll
        for (int j = 0; j < 4; j++) acc[i][j] = 0.0f;

    // ldmatrix per-thread offsets (within a buffer)
    int grp = lane >> 3, i8 = lane & 7;
    int gw = (wid & 3) * 16;
    int fh = (wid >> 2) * 64;
    uint32_t aOff = (uint32_t)(((gw + i8 + ((grp & 1) ? 8 : 0)) * 40 + ((grp & 2) ? 8 : 0)) * 2);
    uint32_t bOff = (uint32_t)(((i8 + ((grp & 1) ? 8 : 0)) * 136 + fh + ((grp & 2) ? 8 : 0)) * 2);
    uint32_t aBuf[2] = {smem_u32(sA[0]), smem_u32(sA[1])};
    uint32_t bBuf[2] = {smem_u32(sB[0]), smem_u32(sB[1])};

    // staging roles
    int g4  = tid >> 4;            // 0..15 -> g rows g4*4..+4     (A staging)
    int kk2 = (tid & 15) * 2;      // 0..30 even k                 (A staging)
    int kkB = tid >> 3;            // 0..31 k row                  (B staging)
    int fs  = (tid & 7) * 16;      // 0..112 f segment             (B staging)

    __syncthreads();   // sW/sb visible

    auto stage = [&](int buf, int c) {
        int k0 = c * 32;
        // A: transpose C[32k x 64g] fp32 -> sA[64g x 32k] bf16
        const float* r0 = g_C + (size_t)(k0 + kk2) * G_NUM + g4 * 4;
        float4 c0 = *(const float4*)r0;
        float4 c1 = *(const float4*)(r0 + G_NUM);
        __nv_bfloat16* abase = sA[buf] + (g4 * 4) * 40 + kk2;
        *(__nv_bfloat162*)(abase + 0 * 40) = __floats2bfloat162_rn(c0.x, c1.x);
        *(__nv_bfloat162*)(abase + 1 * 40) = __floats2bfloat162_rn(c0.y, c1.y);
        *(__nv_bfloat162*)(abase + 2 * 40) = __floats2bfloat162_rn(c0.z, c1.z);
        *(__nv_bfloat162*)(abase + 3 * 40) = __floats2bfloat162_rn(c0.w, c1.w);
        // B: h row kkB, f in [fs, fs+16)  (fused layer-1 epilogue)
        float4 ag = ((const float4*)g_agg3)[k0 + kkB];
        float dv = ag.w;
        float a0 = ag.x * dv, a1 = ag.y * dv, a2 = ag.z * dv;
        uint32_t outp[8];
#pragma unroll
        for (int m = 0; m < 4; m++) {
            int f = fs + m * 4;
            float4 w0 = *(const float4*)(sW + f);
            float4 w1 = *(const float4*)(sW + D + f);
            float4 w2 = *(const float4*)(sW + 2 * D + f);
            float4 bv = *(const float4*)(sb + f);
            float h0 = dv * fmaxf(bv.x + a0 * w0.x + a1 * w1.x + a2 * w2.x, 0.f);
            float h1 = dv * fmaxf(bv.y + a0 * w0.y + a1 * w1.y + a2 * w2.y, 0.f);
            float h2 = dv * fmaxf(bv.z + a0 * w0.z + a1 * w1.z + a2 * w2.z, 0.f);
            float h3 = dv * fmaxf(bv.w + a0 * w0.w + a1 * w1.w + a2 * w2.w, 0.f);
            __nv_bfloat162 pa = __floats2bfloat162_rn(h0, h1);
            __nv_bfloat162 pb = __floats2bfloat162_rn(h2, h3);
            outp[m * 2]     = *(uint32_t*)&pa;
            outp[m * 2 + 1] = *(uint32_t*)&pb;
        }
        *(uint4*)(sB[buf] + kkB * 136 + fs)     = make_uint4(outp[0], outp[1], outp[2], outp[3]);
        *(uint4*)(sB[buf] + kkB * 136 + fs + 8) = make_uint4(outp[4], outp[5], outp[6], outp[7]);
    };

    // prologue
    stage(0, blockIdx.x);
    __syncthreads();

    int cur = 0;
    for (int c = blockIdx.x; c < NCHUNK32; c += MGRID) {
        int cn = c + MGRID;
        if (cn < NCHUNK32) stage(cur ^ 1, cn);     // overlaps with MMAs below

#pragma unroll
        for (int s = 0; s < 2; s++) {
            uint32_t a[4];
            asm volatile("ldmatrix.sync.aligned.m8n8.x4.shared.b16 {%0,%1,%2,%3}, [%4];"
                         : "=r"(a[0]), "=r"(a[1]), "=r"(a[2]), "=r"(a[3])
                         : "r"(aBuf[cur] + aOff + s * 32));
#pragma unroll
            for (int nt4 = 0; nt4 < 4; nt4++) {
                uint32_t b[4];
                asm volatile("ldmatrix.sync.aligned.m8n8.x4.trans.shared.b16 {%0,%1,%2,%3}, [%4];"
                             : "=r"(b[0]), "=r"(b[1]), "=r"(b[2]), "=r"(b[3])
                             : "r"(bBuf[cur] + bOff + (uint32_t)(s * 16 * 136 * 2 + nt4 * 32)));
                int nt = nt4 * 2;
                asm volatile("mma.sync.aligned.m16n8k16.row.col.f32.bf16.bf16.f32 "
                             "{%0,%1,%2,%3}, {%4,%5,%6,%7}, {%8,%9}, {%0,%1,%2,%3};"
                             : "+f"(acc[nt][0]), "+f"(acc[nt][1]), "+f"(acc[nt][2]), "+f"(acc[nt][3])
                             : "r"(a[0]), "r"(a[1]), "r"(a[2]), "r"(a[3]), "r"(b[0]), "r"(b[1]));
                asm volatile("mma.sync.aligned.m16n8k16.row.col.f32.bf16.bf16.f32 "
                             "{%0,%1,%2,%3}, {%4,%5,%6,%7}, {%8,%9}, {%0,%1,%2,%3};"
                             : "+f"(acc[nt+1][0]), "+f"(acc[nt+1][1]), "+f"(acc[nt+1][2]), "+f"(acc[nt+1][3])
                             : "r"(a[0]), "r"(a[1]), "r"(a[2]), "r"(a[3]), "r"(b[2]), "r"(b[3]));
            }
        }
        __syncthreads();
        cur ^= 1;
    }

    // epilogue: red accumulators into g_T
    int gRow = gw + (lane >> 2);
    int fc = fh + (lane & 3) * 2;
#pragma unroll
    for (int nt = 0; nt < 8; nt++) {
        red_add_v2(&g_T[gRow * D + fc + nt * 8],       acc[nt][0], acc[nt][1]);
        red_add_v2(&g_T[(gRow + 8) * D + fc + nt * 8], acc[nt][2], acc[nt][3]);
    }
}

// ---------------- mean + @W2+b2 + @Wf+bf  (block per graph, 512 thr) ----------------
__global__ __launch_bounds__(512) void k_pwq(const float* __restrict__ W2,
                                             const float* __restrict__ b2,
                                             const float* __restrict__ Wf,
                                             const float* __restrict__ bf,
                                             float* __restrict__ q) {
    __shared__ float sT[D];
    __shared__ float sge[D];
    int g = blockIdx.x;
    int tid = threadIdx.x;    // 512

    if (tid < D) {
        float cnt = fmaxf((float)g_cntg[g], 1.0f);
        sT[tid] = g_T[g * D + tid] / cnt;
    }
    __syncthreads();

    if (tid < D) {
        float acc = b2[tid];
#pragma unroll 16
        for (int k = 0; k < D; k++) acc += sT[k] * W2[k * D + tid];
        sge[tid] = acc;
    }
    __syncthreads();

    {
        int a = tid;            // 512 threads == A_DIM outputs
        float acc = bf[a];
#pragma unroll 16
        for (int k = 0; k < D; k++) acc += sge[k] * Wf[k * A_DIM + a];
        q[g * A_DIM + a] = acc;
    }
}

// ---------------- launch ----------------
extern "C" void kernel_launch(void* const* d_in, const int* in_sizes, int n_in,
                              void* d_out, int out_size) {
    const float* x     = (const float*)d_in[0];
    const int*   ei    = (const int*)  d_in[1];
    const int*   batch = (const int*)  d_in[2];
    const float* W1    = (const float*)d_in[3];
    const float* b1    = (const float*)d_in[4];
    const float* W2    = (const float*)d_in[5];
    const float* b2    = (const float*)d_in[6];
    const float* Wf    = (const float*)d_in[7];
    const float* bf    = (const float*)d_in[8];
    float* q = (float*)d_out;

    const int* src = ei;
    const int* dst = ei + N_EDGES;

    void* pc;
    cudaGetSymbolAddress(&pc, g_cnt);
    cudaMemsetAsync(pc, 0, N_NODES * sizeof(int));

    k_hist<<<(N_EDGES + 255) / 256, 256>>>(dst);
    k_dis_init<<<(N_NODES * 16 + 255) / 256, 256>>>(x, batch);
    k_edge<<<(N_EDGES + 255) / 256, 256>>>(src, dst);
    k_mma<<<MGRID, 256>>>(W1, b1);
    k_pwq<<<G_NUM, 512>>>(W2, b2, Wf, bf, q);
}